// round 1
// baseline (speedup 1.0000x reference)
#include <cuda_runtime.h>

#define B_ 4
#define NH 8
#define D_ 32
#define C_ 256
#define O3_ 768
#define N_ 4096
#define NM_ 4
#define S_TOT 4100
#define SCALE_ 0.17677669529663687f

// Static device scratch (allocation-free per harness rules)
__device__ float g_Q[(size_t)B_ * NH * D_ * N_];      // [bh][d][n], pre-scaled by SCALE
__device__ float g_K[(size_t)B_ * NH * D_ * S_TOT];   // [bh][d][s]
__device__ float g_Vt[(size_t)B_ * NH * S_TOT * D_];  // [bh][s][d]
__device__ float g_Onn[(size_t)B_ * N_ * C_];         // [b][n][c]  (c = head*32+d)

// ---------------------------------------------------------------------------
// QKV projection: y[b][o][p] = sum_c w[o][c] * x[b][c][p] + bias[o]
// Scatter epilogue into g_Q / g_K / g_Vt.
// ---------------------------------------------------------------------------
__global__ __launch_bounds__(256) void qkv_kernel(
    const float* __restrict__ x, const float* __restrict__ w,
    const float* __restrict__ bias) {
  __shared__ float Ws[32][64];  // [c][o]
  __shared__ float Xs[32][64];  // [c][p]
  int b = blockIdx.z;
  int ob = blockIdx.y * 64;
  int pb = blockIdx.x * 64;
  int tid = threadIdx.x;
  int tx = tid & 15, ty = tid >> 4;
  float acc[4][4];
#pragma unroll
  for (int a = 0; a < 4; a++)
#pragma unroll
    for (int e = 0; e < 4; e++) acc[a][e] = 0.f;

  const float* xb = x + (size_t)b * C_ * N_;
  int r = tid >> 2;
  int c8 = (tid & 3) * 8;

  for (int kk = 0; kk < C_; kk += 32) {
    // W tile [64 o][32 c] -> Ws[c][o] (transposed store)
    float4 w0 = *(const float4*)(w + (size_t)(ob + r) * C_ + kk + c8);
    float4 w1 = *(const float4*)(w + (size_t)(ob + r) * C_ + kk + c8 + 4);
    Ws[c8 + 0][r] = w0.x; Ws[c8 + 1][r] = w0.y; Ws[c8 + 2][r] = w0.z; Ws[c8 + 3][r] = w0.w;
    Ws[c8 + 4][r] = w1.x; Ws[c8 + 5][r] = w1.y; Ws[c8 + 6][r] = w1.z; Ws[c8 + 7][r] = w1.w;
    // X tile [32 c][64 p], already c-major in global
#pragma unroll
    for (int q = 0; q < 2; q++) {
      int f4 = tid + q * 256;
      int c = f4 >> 4, p4 = (f4 & 15) * 4;
      *(float4*)&Xs[c][p4] =
          *(const float4*)(xb + (size_t)(kk + c) * N_ + pb + p4);
    }
    __syncthreads();
#pragma unroll
    for (int c = 0; c < 32; c++) {
      float4 wa = *(float4*)&Ws[c][ty * 4];
      float4 xv = *(float4*)&Xs[c][tx * 4];
      float wr[4] = {wa.x, wa.y, wa.z, wa.w};
      float xr[4] = {xv.x, xv.y, xv.z, xv.w};
#pragma unroll
      for (int a = 0; a < 4; a++)
#pragma unroll
        for (int e = 0; e < 4; e++) acc[a][e] += wr[a] * xr[e];
    }
    __syncthreads();
  }

#pragma unroll
  for (int a = 0; a < 4; a++) {
    int o = ob + ty * 4 + a;
    float bv = bias[o];
    float4 rv;
    rv.x = acc[a][0] + bv; rv.y = acc[a][1] + bv;
    rv.z = acc[a][2] + bv; rv.w = acc[a][3] + bv;
    int p = pb + tx * 4;
    int region = o >> 8;
    int rem = o & 255;
    int hh = rem >> 5, dd = rem & 31;
    int bh = b * NH + hh;
    if (region == 0) {
      rv.x *= SCALE_; rv.y *= SCALE_; rv.z *= SCALE_; rv.w *= SCALE_;
      *(float4*)(g_Q + ((size_t)bh * D_ + dd) * N_ + p) = rv;
    } else if (region == 1) {
      *(float4*)(g_K + ((size_t)bh * D_ + dd) * S_TOT + NM_ + p) = rv;
    } else {
      float* vb = g_Vt + ((size_t)bh * S_TOT + NM_ + p) * D_ + dd;
      vb[0] = rv.x; vb[D_] = rv.y; vb[2 * D_] = rv.z; vb[3 * D_] = rv.w;
    }
  }
}

// ---------------------------------------------------------------------------
// Scatter the 4 memory kv tokens into s = 0..3 of g_K / g_Vt for every batch.
// mem_kv layout: (2, NH, NM, D)
// ---------------------------------------------------------------------------
__global__ void memtok_kernel(const float* __restrict__ mem_kv) {
  int idx = blockIdx.x * blockDim.x + threadIdx.x;
  if (idx >= 2 * NH * NM_ * D_) return;
  int d = idx & 31, mm = (idx >> 5) & 3, hh = (idx >> 7) & 7, kv = idx >> 10;
  float v = mem_kv[idx];
#pragma unroll
  for (int b = 0; b < B_; b++) {
    int bh = b * NH + hh;
    if (kv == 0)
      g_K[((size_t)bh * D_ + d) * S_TOT + mm] = v;
    else
      g_Vt[((size_t)bh * S_TOT + mm) * D_ + d] = v;
  }
}

// ---------------------------------------------------------------------------
// Flash attention, fp32 SIMT. 128 threads, 64-query tile, stream 64-key tiles.
// S-phase: thread = (ty 0..7, tx 0..15), 8 rows x 4 cols micro-tile.
// PV-phase: thread = (typ 0..15, txp 0..7), 4 rows x 4 dv micro-tile.
// ---------------------------------------------------------------------------
__global__ __launch_bounds__(128) void attn_kernel() {
  __shared__ float Qs[32][64];   // [d][i]
  __shared__ float Ks[32][64];   // [d][j]
  __shared__ float Vs[64][32];   // [j][d]
  __shared__ float Ps[64][68];   // [j][i] (+pad)
  __shared__ float alpha_s[64];
  __shared__ float l_s[64];

  int b = blockIdx.z, h = blockIdx.y;
  int qbase = blockIdx.x * 64;
  int tid = threadIdx.x;
  int tx = tid & 15, ty = tid >> 4;
  int typ = tid >> 3, txp = tid & 7;

  int bh = b * NH + h;
  const float* Qg = g_Q + (size_t)bh * D_ * N_;
  const float* Kg = g_K + (size_t)bh * D_ * S_TOT;
  const float* Vg = g_Vt + (size_t)bh * S_TOT * D_;

  // Load Q tile [32][64]
#pragma unroll
  for (int q = 0; q < 4; q++) {
    int f4 = tid + q * 128;
    int d = f4 >> 4, p4 = (f4 & 15) * 4;
    *(float4*)&Qs[d][p4] = *(const float4*)(Qg + (size_t)d * N_ + qbase + p4);
  }

  float m[8], l[8], Oa[4][4];
#pragma unroll
  for (int a = 0; a < 8; a++) { m[a] = -1e30f; l[a] = 0.f; }
#pragma unroll
  for (int a = 0; a < 4; a++)
#pragma unroll
    for (int e = 0; e < 4; e++) Oa[a][e] = 0.f;

  const int NTILES = (S_TOT + 63) / 64;  // 65
  for (int t = 0; t < NTILES; t++) {
    int kbase = t * 64;
    __syncthreads();  // prev PV done before overwriting Ks/Vs/Ps

    // Load K tile [32][64]
#pragma unroll
    for (int q = 0; q < 4; q++) {
      int f4 = tid + q * 128;
      int d = f4 >> 4, j4 = (f4 & 15) * 4;
      float4 v = make_float4(0.f, 0.f, 0.f, 0.f);
      if (kbase + j4 < S_TOT)
        v = *(const float4*)(Kg + (size_t)d * S_TOT + kbase + j4);
      *(float4*)&Ks[d][j4] = v;
    }
    // Load V tile [64][32]
#pragma unroll
    for (int q = 0; q < 4; q++) {
      int f4 = tid + q * 128;
      int j = f4 >> 3, d4 = (f4 & 7) * 4;
      float4 v = make_float4(0.f, 0.f, 0.f, 0.f);
      if (kbase + j < S_TOT)
        v = *(const float4*)(Vg + (size_t)(kbase + j) * D_ + d4);
      *(float4*)&Vs[j][d4] = v;
    }
    __syncthreads();

    // S = Q^T K  (8x4 per thread)
    float s[8][4];
#pragma unroll
    for (int a = 0; a < 8; a++)
#pragma unroll
      for (int bb = 0; bb < 4; bb++) s[a][bb] = 0.f;
#pragma unroll
    for (int d = 0; d < 32; d++) {
      float4 q0 = *(float4*)&Qs[d][ty * 8];
      float4 q1 = *(float4*)&Qs[d][ty * 8 + 4];
      float4 kv4 = *(float4*)&Ks[d][tx * 4];
      float qr[8] = {q0.x, q0.y, q0.z, q0.w, q1.x, q1.y, q1.z, q1.w};
      float kr[4] = {kv4.x, kv4.y, kv4.z, kv4.w};
#pragma unroll
      for (int a = 0; a < 8; a++)
#pragma unroll
        for (int bb = 0; bb < 4; bb++) s[a][bb] += qr[a] * kr[bb];
    }
    // Mask out-of-range keys (only last tile)
    if (kbase + 64 > S_TOT) {
#pragma unroll
      for (int bb = 0; bb < 4; bb++)
        if (kbase + tx * 4 + bb >= S_TOT) {
#pragma unroll
          for (int a = 0; a < 8; a++) s[a][bb] = -1e30f;
        }
    }

    // Online softmax (row groups of 16 lanes: xor 8,4,2,1 stays in-group)
#pragma unroll
    for (int a = 0; a < 8; a++) {
      float tm = fmaxf(fmaxf(s[a][0], s[a][1]), fmaxf(s[a][2], s[a][3]));
#pragma unroll
      for (int off = 8; off; off >>= 1)
        tm = fmaxf(tm, __shfl_xor_sync(0xffffffffu, tm, off));
      float mn = fmaxf(m[a], tm);
      float al0 = __expf(m[a] - mn);
      m[a] = mn;
      float rs = 0.f;
#pragma unroll
      for (int bb = 0; bb < 4; bb++) {
        float p = __expf(s[a][bb] - mn);
        s[a][bb] = p;
        rs += p;
      }
#pragma unroll
      for (int off = 8; off; off >>= 1)
        rs += __shfl_xor_sync(0xffffffffu, rs, off);
      l[a] = l[a] * al0 + rs;
      if (tx == 0) alpha_s[ty * 8 + a] = al0;
    }

    // Store P transposed: Ps[j][i], vectorized along i (conflict-free)
#pragma unroll
    for (int bb = 0; bb < 4; bb++) {
      int j = tx * 4 + bb;
      float4 v0 = make_float4(s[0][bb], s[1][bb], s[2][bb], s[3][bb]);
      float4 v1 = make_float4(s[4][bb], s[5][bb], s[6][bb], s[7][bb]);
      *(float4*)&Ps[j][ty * 8] = v0;
      *(float4*)&Ps[j][ty * 8 + 4] = v1;
    }
    __syncthreads();

    // PV accumulate: O[i][dv] = O[i][dv]*alpha + sum_j P[j][i] * V[j][dv]
    float al[4];
#pragma unroll
    for (int aa = 0; aa < 4; aa++) al[aa] = alpha_s[typ * 4 + aa];
#pragma unroll
    for (int aa = 0; aa < 4; aa++)
#pragma unroll
      for (int e = 0; e < 4; e++) Oa[aa][e] *= al[aa];

#pragma unroll 8
    for (int j = 0; j < 64; j++) {
      float4 pv = *(float4*)&Ps[j][typ * 4];
      float4 vv = *(float4*)&Vs[j][txp * 4];
      float pr[4] = {pv.x, pv.y, pv.z, pv.w};
      float vr[4] = {vv.x, vv.y, vv.z, vv.w};
#pragma unroll
      for (int aa = 0; aa < 4; aa++)
#pragma unroll
        for (int e = 0; e < 4; e++) Oa[aa][e] += pr[aa] * vr[e];
    }
  }

  // Publish final row sums, normalize, write out [b][n][c]
  if (tx == 0) {
#pragma unroll
    for (int a = 0; a < 8; a++) l_s[ty * 8 + a] = l[a];
  }
  __syncthreads();
#pragma unroll
  for (int aa = 0; aa < 4; aa++) {
    int i = typ * 4 + aa;
    float inv = 1.0f / l_s[i];
    float4 o;
    o.x = Oa[aa][0] * inv; o.y = Oa[aa][1] * inv;
    o.z = Oa[aa][2] * inv; o.w = Oa[aa][3] * inv;
    *(float4*)(g_Onn + ((size_t)b * N_ + qbase + i) * C_ + h * D_ + txp * 4) = o;
  }
}

// ---------------------------------------------------------------------------
// Output projection: out[b][o][p] = sum_c g_Onn[b][p][c] * w_out[o][c] + b_out[o]
// ---------------------------------------------------------------------------
__global__ __launch_bounds__(256) void outproj_kernel(
    const float* __restrict__ w, const float* __restrict__ bias,
    float* __restrict__ out) {
  __shared__ float Ws[32][64];  // [c][o]
  __shared__ float As[32][64];  // [c][p]
  int b = blockIdx.z;
  int ob = blockIdx.y * 64;
  int pb = blockIdx.x * 64;
  int tid = threadIdx.x;
  int tx = tid & 15, ty = tid >> 4;
  float acc[4][4];
#pragma unroll
  for (int a = 0; a < 4; a++)
#pragma unroll
    for (int e = 0; e < 4; e++) acc[a][e] = 0.f;

  const float* Ob = g_Onn + (size_t)b * N_ * C_;
  int r = tid >> 2;
  int c8 = (tid & 3) * 8;

  for (int kk = 0; kk < C_; kk += 32) {
    float4 w0 = *(const float4*)(w + (size_t)(ob + r) * C_ + kk + c8);
    float4 w1 = *(const float4*)(w + (size_t)(ob + r) * C_ + kk + c8 + 4);
    Ws[c8 + 0][r] = w0.x; Ws[c8 + 1][r] = w0.y; Ws[c8 + 2][r] = w0.z; Ws[c8 + 3][r] = w0.w;
    Ws[c8 + 4][r] = w1.x; Ws[c8 + 5][r] = w1.y; Ws[c8 + 6][r] = w1.z; Ws[c8 + 7][r] = w1.w;

    float4 a0 = *(const float4*)(Ob + (size_t)(pb + r) * C_ + kk + c8);
    float4 a1 = *(const float4*)(Ob + (size_t)(pb + r) * C_ + kk + c8 + 4);
    As[c8 + 0][r] = a0.x; As[c8 + 1][r] = a0.y; As[c8 + 2][r] = a0.z; As[c8 + 3][r] = a0.w;
    As[c8 + 4][r] = a1.x; As[c8 + 5][r] = a1.y; As[c8 + 6][r] = a1.z; As[c8 + 7][r] = a1.w;
    __syncthreads();
#pragma unroll
    for (int c = 0; c < 32; c++) {
      float4 wa = *(float4*)&Ws[c][ty * 4];
      float4 av = *(float4*)&As[c][tx * 4];
      float wr[4] = {wa.x, wa.y, wa.z, wa.w};
      float ar[4] = {av.x, av.y, av.z, av.w};
#pragma unroll
      for (int a = 0; a < 4; a++)
#pragma unroll
        for (int e = 0; e < 4; e++) acc[a][e] += wr[a] * ar[e];
    }
    __syncthreads();
  }

#pragma unroll
  for (int a = 0; a < 4; a++) {
    int o = ob + ty * 4 + a;
    float bv = bias[o];
    float4 rv;
    rv.x = acc[a][0] + bv; rv.y = acc[a][1] + bv;
    rv.z = acc[a][2] + bv; rv.w = acc[a][3] + bv;
    *(float4*)(out + ((size_t)(b * C_ + o)) * N_ + pb + tx * 4) = rv;
  }
}

// ---------------------------------------------------------------------------
extern "C" void kernel_launch(void* const* d_in, const int* in_sizes, int n_in,
                              void* d_out, int out_size) {
  const float* x = (const float*)d_in[0];
  const float* w_qkv = (const float*)d_in[1];
  const float* b_qkv = (const float*)d_in[2];
  const float* mem_kv = (const float*)d_in[3];
  const float* w_out = (const float*)d_in[4];
  const float* b_out = (const float*)d_in[5];
  float* out = (float*)d_out;

  dim3 g1(N_ / 64, O3_ / 64, B_);  // 64 x 12 x 4
  qkv_kernel<<<g1, 256>>>(x, w_qkv, b_qkv);

  memtok_kernel<<<2, 1024>>>(mem_kv);

  dim3 g2(N_ / 64, NH, B_);  // 64 x 8 x 4
  attn_kernel<<<g2, 128>>>();

  dim3 g3(N_ / 64, C_ / 64, B_);  // 64 x 4 x 4
  outproj_kernel<<<g3, 256>>>(w_out, b_out, out);
}

// round 2
// speedup vs baseline: 2.3291x; 2.3291x over previous
#include <cuda_runtime.h>

#define B_ 4
#define NH 8
#define D_ 32
#define C_ 256
#define O3_ 768
#define N_ 4096
#define NM_ 4
#define S_TOT 4100
#define SCALE_ 0.17677669529663687f

// Static device scratch (allocation-free per harness rules)
__device__ float g_Q[(size_t)B_ * NH * D_ * N_];      // [bh][d][n], pre-scaled by SCALE
__device__ float g_K[(size_t)B_ * NH * D_ * S_TOT];   // [bh][d][s]
__device__ float g_Vt[(size_t)B_ * NH * S_TOT * D_];  // [bh][s][d]
__device__ float g_Onn[(size_t)B_ * N_ * C_];         // [b][n][c]  (c = head*32+d)

// ---------------------------------------------------------------------------
// tf32 helpers
// ---------------------------------------------------------------------------
__device__ __forceinline__ float to_tf32(float x) {
  float r;
  asm("cvt.rna.tf32.f32 %0, %1;" : "=f"(r) : "f"(x));
  return r;
}

__device__ __forceinline__ void mma_tf32(float c[4], const float a[4],
                                         float b0, float b1) {
  asm volatile(
      "mma.sync.aligned.m16n8k8.row.col.f32.tf32.tf32.f32 "
      "{%0,%1,%2,%3}, {%4,%5,%6,%7}, {%8,%9}, {%0,%1,%2,%3};\n"
      : "+f"(c[0]), "+f"(c[1]), "+f"(c[2]), "+f"(c[3])
      : "r"(__float_as_uint(a[0])), "r"(__float_as_uint(a[1])),
        "r"(__float_as_uint(a[2])), "r"(__float_as_uint(a[3])),
        "r"(__float_as_uint(b0)), "r"(__float_as_uint(b1)));
}

// ---------------------------------------------------------------------------
// QKV projection: y[b][o][p] = sum_c w[o][c] * x[b][c][p] + bias[o]
// Scatter epilogue into g_Q / g_K / g_Vt.
// ---------------------------------------------------------------------------
__global__ __launch_bounds__(256) void qkv_kernel(
    const float* __restrict__ x, const float* __restrict__ w,
    const float* __restrict__ bias) {
  __shared__ float Ws[32][64];  // [c][o]
  __shared__ float Xs[32][64];  // [c][p]
  int b = blockIdx.z;
  int ob = blockIdx.y * 64;
  int pb = blockIdx.x * 64;
  int tid = threadIdx.x;
  int tx = tid & 15, ty = tid >> 4;
  float acc[4][4];
#pragma unroll
  for (int a = 0; a < 4; a++)
#pragma unroll
    for (int e = 0; e < 4; e++) acc[a][e] = 0.f;

  const float* xb = x + (size_t)b * C_ * N_;
  int r = tid >> 2;
  int c8 = (tid & 3) * 8;

  for (int kk = 0; kk < C_; kk += 32) {
    float4 w0 = *(const float4*)(w + (size_t)(ob + r) * C_ + kk + c8);
    float4 w1 = *(const float4*)(w + (size_t)(ob + r) * C_ + kk + c8 + 4);
    Ws[c8 + 0][r] = w0.x; Ws[c8 + 1][r] = w0.y; Ws[c8 + 2][r] = w0.z; Ws[c8 + 3][r] = w0.w;
    Ws[c8 + 4][r] = w1.x; Ws[c8 + 5][r] = w1.y; Ws[c8 + 6][r] = w1.z; Ws[c8 + 7][r] = w1.w;
#pragma unroll
    for (int q = 0; q < 2; q++) {
      int f4 = tid + q * 256;
      int c = f4 >> 4, p4 = (f4 & 15) * 4;
      *(float4*)&Xs[c][p4] =
          *(const float4*)(xb + (size_t)(kk + c) * N_ + pb + p4);
    }
    __syncthreads();
#pragma unroll
    for (int c = 0; c < 32; c++) {
      float4 wa = *(float4*)&Ws[c][ty * 4];
      float4 xv = *(float4*)&Xs[c][tx * 4];
      float wr[4] = {wa.x, wa.y, wa.z, wa.w};
      float xr[4] = {xv.x, xv.y, xv.z, xv.w};
#pragma unroll
      for (int a = 0; a < 4; a++)
#pragma unroll
        for (int e = 0; e < 4; e++) acc[a][e] += wr[a] * xr[e];
    }
    __syncthreads();
  }

#pragma unroll
  for (int a = 0; a < 4; a++) {
    int o = ob + ty * 4 + a;
    float bv = bias[o];
    float4 rv;
    rv.x = acc[a][0] + bv; rv.y = acc[a][1] + bv;
    rv.z = acc[a][2] + bv; rv.w = acc[a][3] + bv;
    int p = pb + tx * 4;
    int region = o >> 8;
    int rem = o & 255;
    int hh = rem >> 5, dd = rem & 31;
    int bh = b * NH + hh;
    if (region == 0) {
      rv.x *= SCALE_; rv.y *= SCALE_; rv.z *= SCALE_; rv.w *= SCALE_;
      *(float4*)(g_Q + ((size_t)bh * D_ + dd) * N_ + p) = rv;
    } else if (region == 1) {
      *(float4*)(g_K + ((size_t)bh * D_ + dd) * S_TOT + NM_ + p) = rv;
    } else {
      float* vb = g_Vt + ((size_t)bh * S_TOT + NM_ + p) * D_ + dd;
      vb[0] = rv.x; vb[D_] = rv.y; vb[2 * D_] = rv.z; vb[3 * D_] = rv.w;
    }
  }
}

// ---------------------------------------------------------------------------
// Scatter the 4 memory kv tokens into s = 0..3 of g_K / g_Vt for every batch.
// ---------------------------------------------------------------------------
__global__ void memtok_kernel(const float* __restrict__ mem_kv) {
  int idx = blockIdx.x * blockDim.x + threadIdx.x;
  if (idx >= 2 * NH * NM_ * D_) return;
  int d = idx & 31, mm = (idx >> 5) & 3, hh = (idx >> 7) & 7, kv = idx >> 10;
  float v = mem_kv[idx];
#pragma unroll
  for (int b = 0; b < B_; b++) {
    int bh = b * NH + hh;
    if (kv == 0)
      g_K[((size_t)bh * D_ + d) * S_TOT + mm] = v;
    else
      g_Vt[((size_t)bh * S_TOT + mm) * D_ + d] = v;
  }
}

// ---------------------------------------------------------------------------
// Flash attention with tf32 mma.sync tensor cores.
// CTA: 256 threads (8 warps). Q-tile = 128 rows (16 per warp). K-tile = 64.
// S = Q K^T via m16n8k8 tf32; online softmax in registers;
// P converted C-frag -> A-frag with intra-warp shuffles (no smem round trip);
// O += P V via m16n8k8 tf32.
// ---------------------------------------------------------------------------
#define KSTRIDE 72   // Ks row stride (floats): conflict-free frag loads
#define VSTRIDE 40   // Vs row stride
#define QSTRIDE 136  // Qs row stride

__global__ __launch_bounds__(256) void attn_mma_kernel() {
  __shared__ float Qs[32 * QSTRIDE];  // [d][i] i=0..127
  __shared__ float Ks[32 * KSTRIDE];  // [d][j] j=0..63
  __shared__ float Vs[64 * VSTRIDE];  // [j][dv] dv=0..31

  int b = blockIdx.z, h = blockIdx.y;
  int bh = b * NH + h;
  int qbase = blockIdx.x * 128;
  int tid = threadIdx.x;
  int lane = tid & 31, w = tid >> 5;
  int g = lane >> 2, t4 = lane & 3;

  const float* Qg = g_Q + (size_t)bh * D_ * N_;
  const float* Kg = g_K + (size_t)bh * D_ * S_TOT;
  const float* Vg = g_Vt + (size_t)bh * S_TOT * D_;

  // ---- Stage Q tile [32 d][128 i] into smem (tf32-rounded) ----
#pragma unroll
  for (int q = 0; q < 4; q++) {
    int idx = tid + q * 256;
    int d = idx >> 5, i4 = (idx & 31) * 4;
    float4 v = *(const float4*)(Qg + (size_t)d * N_ + qbase + i4);
    v.x = to_tf32(v.x); v.y = to_tf32(v.y);
    v.z = to_tf32(v.z); v.w = to_tf32(v.w);
    *(float4*)&Qs[d * QSTRIDE + i4] = v;
  }
  __syncthreads();

  // ---- Q A-fragments in registers: qa[kt][4], kt covers d = 8kt..8kt+7 ----
  float qa[4][4];
  {
    int i0 = 16 * w + g;
#pragma unroll
    for (int kt = 0; kt < 4; kt++) {
      int d0 = 8 * kt + t4;
      qa[kt][0] = Qs[d0 * QSTRIDE + i0];
      qa[kt][1] = Qs[d0 * QSTRIDE + i0 + 8];
      qa[kt][2] = Qs[(d0 + 4) * QSTRIDE + i0];
      qa[kt][3] = Qs[(d0 + 4) * QSTRIDE + i0 + 8];
    }
  }

  float oc[4][4];
#pragma unroll
  for (int nt = 0; nt < 4; nt++)
#pragma unroll
    for (int e = 0; e < 4; e++) oc[nt][e] = 0.f;
  float m0 = -1e30f, m1 = -1e30f, l0 = 0.f, l1 = 0.f;

  const int NTILES = (S_TOT + 63) / 64;  // 65
#pragma unroll 1
  for (int t = 0; t < NTILES; t++) {
    int kbase = t * 64;
    __syncthreads();  // previous tile fully consumed

    // ---- Load K tile [32][64] ----
#pragma unroll
    for (int q = 0; q < 2; q++) {
      int idx = tid + q * 256;
      int d = idx >> 4, j4 = (idx & 15) * 4;
      float4 v = make_float4(0.f, 0.f, 0.f, 0.f);
      if (kbase + j4 < S_TOT)
        v = *(const float4*)(Kg + (size_t)d * S_TOT + kbase + j4);
      v.x = to_tf32(v.x); v.y = to_tf32(v.y);
      v.z = to_tf32(v.z); v.w = to_tf32(v.w);
      *(float4*)&Ks[d * KSTRIDE + j4] = v;
    }
    // ---- Load V tile [64][32] ----
#pragma unroll
    for (int q = 0; q < 2; q++) {
      int idx = tid + q * 256;
      int j = idx >> 3, d4 = (idx & 7) * 4;
      float4 v = make_float4(0.f, 0.f, 0.f, 0.f);
      if (kbase + j < S_TOT)
        v = *(const float4*)(Vg + (size_t)(kbase + j) * D_ + d4);
      v.x = to_tf32(v.x); v.y = to_tf32(v.y);
      v.z = to_tf32(v.z); v.w = to_tf32(v.w);
      *(float4*)&Vs[j * VSTRIDE + d4] = v;
    }
    __syncthreads();

    // ---- S = Q K^T : sc[nt] covers keys 8nt..8nt+7 ----
    float sc[8][4];
#pragma unroll
    for (int nt = 0; nt < 8; nt++)
#pragma unroll
      for (int e = 0; e < 4; e++) sc[nt][e] = 0.f;
#pragma unroll
    for (int kt = 0; kt < 4; kt++) {
#pragma unroll
      for (int nt = 0; nt < 8; nt++) {
        float b0 = Ks[(8 * kt + t4) * KSTRIDE + 8 * nt + g];
        float b1 = Ks[(8 * kt + t4 + 4) * KSTRIDE + 8 * nt + g];
        mma_tf32(sc[nt], qa[kt], b0, b1);
      }
    }

    // ---- Mask invalid keys (only last tile) ----
    if (kbase + 64 > S_TOT) {
#pragma unroll
      for (int nt = 0; nt < 8; nt++) {
        int col = kbase + 8 * nt + 2 * t4;
        if (col >= S_TOT) sc[nt][0] = sc[nt][2] = -1e30f;
        if (col + 1 >= S_TOT) sc[nt][1] = sc[nt][3] = -1e30f;
      }
    }

    // ---- Online softmax (rows g and g+8) ----
    float mx0 = -1e30f, mx1 = -1e30f;
#pragma unroll
    for (int nt = 0; nt < 8; nt++) {
      mx0 = fmaxf(mx0, fmaxf(sc[nt][0], sc[nt][1]));
      mx1 = fmaxf(mx1, fmaxf(sc[nt][2], sc[nt][3]));
    }
    mx0 = fmaxf(mx0, __shfl_xor_sync(0xffffffffu, mx0, 1));
    mx0 = fmaxf(mx0, __shfl_xor_sync(0xffffffffu, mx0, 2));
    mx1 = fmaxf(mx1, __shfl_xor_sync(0xffffffffu, mx1, 1));
    mx1 = fmaxf(mx1, __shfl_xor_sync(0xffffffffu, mx1, 2));
    float mn0 = fmaxf(m0, mx0), mn1 = fmaxf(m1, mx1);
    float al0 = __expf(m0 - mn0), al1 = __expf(m1 - mn1);
    m0 = mn0; m1 = mn1;
    float rs0 = 0.f, rs1 = 0.f;
#pragma unroll
    for (int nt = 0; nt < 8; nt++) {
      sc[nt][0] = __expf(sc[nt][0] - mn0);
      sc[nt][1] = __expf(sc[nt][1] - mn0);
      sc[nt][2] = __expf(sc[nt][2] - mn1);
      sc[nt][3] = __expf(sc[nt][3] - mn1);
      rs0 += sc[nt][0] + sc[nt][1];
      rs1 += sc[nt][2] + sc[nt][3];
    }
    rs0 += __shfl_xor_sync(0xffffffffu, rs0, 1);
    rs0 += __shfl_xor_sync(0xffffffffu, rs0, 2);
    rs1 += __shfl_xor_sync(0xffffffffu, rs1, 1);
    rs1 += __shfl_xor_sync(0xffffffffu, rs1, 2);
    l0 = l0 * al0 + rs0;
    l1 = l1 * al1 + rs1;

    // ---- Rescale O accumulators ----
#pragma unroll
    for (int nt = 0; nt < 4; nt++) {
      oc[nt][0] *= al0; oc[nt][1] *= al0;
      oc[nt][2] *= al1; oc[nt][3] *= al1;
    }

    // ---- PV: convert P C-frag -> A-frag (shuffles), then mma ----
    int srcA = (lane & 28) | (t4 >> 1);
    int srcB = srcA + 2;
    bool odd = (t4 & 1) != 0;
#pragma unroll
    for (int kt = 0; kt < 8; kt++) {
      float x0 = __shfl_sync(0xffffffffu, sc[kt][0], srcA);
      float x1 = __shfl_sync(0xffffffffu, sc[kt][1], srcA);
      float x2 = __shfl_sync(0xffffffffu, sc[kt][2], srcA);
      float x3 = __shfl_sync(0xffffffffu, sc[kt][3], srcA);
      float y0 = __shfl_sync(0xffffffffu, sc[kt][0], srcB);
      float y1 = __shfl_sync(0xffffffffu, sc[kt][1], srcB);
      float y2 = __shfl_sync(0xffffffffu, sc[kt][2], srcB);
      float y3 = __shfl_sync(0xffffffffu, sc[kt][3], srcB);
      float pa[4];
      pa[0] = to_tf32(odd ? x1 : x0);
      pa[1] = to_tf32(odd ? x3 : x2);
      pa[2] = to_tf32(odd ? y1 : y0);
      pa[3] = to_tf32(odd ? y3 : y2);
#pragma unroll
      for (int nt = 0; nt < 4; nt++) {
        float b0 = Vs[(8 * kt + t4) * VSTRIDE + 8 * nt + g];
        float b1 = Vs[(8 * kt + t4 + 4) * VSTRIDE + 8 * nt + g];
        mma_tf32(oc[nt], pa, b0, b1);
      }
    }
  }

  // ---- Normalize and write out: g_Onn[b][n][h*32 + dv] ----
  float inv0 = 1.0f / l0, inv1 = 1.0f / l1;
  int row0 = qbase + 16 * w + g;
  int row1 = row0 + 8;
#pragma unroll
  for (int nt = 0; nt < 4; nt++) {
    int dv = 8 * nt + 2 * t4;
    float2 v0 = make_float2(oc[nt][0] * inv0, oc[nt][1] * inv0);
    float2 v1 = make_float2(oc[nt][2] * inv1, oc[nt][3] * inv1);
    *(float2*)(g_Onn + ((size_t)b * N_ + row0) * C_ + h * D_ + dv) = v0;
    *(float2*)(g_Onn + ((size_t)b * N_ + row1) * C_ + h * D_ + dv) = v1;
  }
}

// ---------------------------------------------------------------------------
// Output projection: out[b][o][p] = sum_c g_Onn[b][p][c] * w_out[o][c] + b_out[o]
// ---------------------------------------------------------------------------
__global__ __launch_bounds__(256) void outproj_kernel(
    const float* __restrict__ w, const float* __restrict__ bias,
    float* __restrict__ out) {
  __shared__ float Ws[32][64];  // [c][o]
  __shared__ float As[32][64];  // [c][p]
  int b = blockIdx.z;
  int ob = blockIdx.y * 64;
  int pb = blockIdx.x * 64;
  int tid = threadIdx.x;
  int tx = tid & 15, ty = tid >> 4;
  float acc[4][4];
#pragma unroll
  for (int a = 0; a < 4; a++)
#pragma unroll
    for (int e = 0; e < 4; e++) acc[a][e] = 0.f;

  const float* Ob = g_Onn + (size_t)b * N_ * C_;
  int r = tid >> 2;
  int c8 = (tid & 3) * 8;

  for (int kk = 0; kk < C_; kk += 32) {
    float4 w0 = *(const float4*)(w + (size_t)(ob + r) * C_ + kk + c8);
    float4 w1 = *(const float4*)(w + (size_t)(ob + r) * C_ + kk + c8 + 4);
    Ws[c8 + 0][r] = w0.x; Ws[c8 + 1][r] = w0.y; Ws[c8 + 2][r] = w0.z; Ws[c8 + 3][r] = w0.w;
    Ws[c8 + 4][r] = w1.x; Ws[c8 + 5][r] = w1.y; Ws[c8 + 6][r] = w1.z; Ws[c8 + 7][r] = w1.w;

    float4 a0 = *(const float4*)(Ob + (size_t)(pb + r) * C_ + kk + c8);
    float4 a1 = *(const float4*)(Ob + (size_t)(pb + r) * C_ + kk + c8 + 4);
    As[c8 + 0][r] = a0.x; As[c8 + 1][r] = a0.y; As[c8 + 2][r] = a0.z; As[c8 + 3][r] = a0.w;
    As[c8 + 4][r] = a1.x; As[c8 + 5][r] = a1.y; As[c8 + 6][r] = a1.z; As[c8 + 7][r] = a1.w;
    __syncthreads();
#pragma unroll
    for (int c = 0; c < 32; c++) {
      float4 wa = *(float4*)&Ws[c][ty * 4];
      float4 av = *(float4*)&As[c][tx * 4];
      float wr[4] = {wa.x, wa.y, wa.z, wa.w};
      float ar[4] = {av.x, av.y, av.z, av.w};
#pragma unroll
      for (int a = 0; a < 4; a++)
#pragma unroll
        for (int e = 0; e < 4; e++) acc[a][e] += wr[a] * ar[e];
    }
    __syncthreads();
  }

#pragma unroll
  for (int a = 0; a < 4; a++) {
    int o = ob + ty * 4 + a;
    float bv = bias[o];
    float4 rv;
    rv.x = acc[a][0] + bv; rv.y = acc[a][1] + bv;
    rv.z = acc[a][2] + bv; rv.w = acc[a][3] + bv;
    *(float4*)(out + ((size_t)(b * C_ + o)) * N_ + pb + tx * 4) = rv;
  }
}

// ---------------------------------------------------------------------------
extern "C" void kernel_launch(void* const* d_in, const int* in_sizes, int n_in,
                              void* d_out, int out_size) {
  const float* x = (const float*)d_in[0];
  const float* w_qkv = (const float*)d_in[1];
  const float* b_qkv = (const float*)d_in[2];
  const float* mem_kv = (const float*)d_in[3];
  const float* w_out = (const float*)d_in[4];
  const float* b_out = (const float*)d_in[5];
  float* out = (float*)d_out;

  dim3 g1(N_ / 64, O3_ / 64, B_);  // 64 x 12 x 4
  qkv_kernel<<<g1, 256>>>(x, w_qkv, b_qkv);

  memtok_kernel<<<2, 1024>>>(mem_kv);

  dim3 g2(N_ / 128, NH, B_);  // 32 x 8 x 4 = 1024 CTAs
  attn_mma_kernel<<<g2, 256>>>();

  dim3 g3(N_ / 64, C_ / 64, B_);  // 64 x 4 x 4
  outproj_kernel<<<g3, 256>>>(w_out, b_out, out);
}

// round 3
// speedup vs baseline: 5.7088x; 2.4510x over previous
#include <cuda_runtime.h>
#include <cuda_fp16.h>
#include <cstdint>

#define B_ 4
#define NH 8
#define D_ 32
#define C_ 256
#define O3_ 768
#define N_ 4096
#define NM_ 4
#define S_TOT 4100
#define SCALE_ 0.17677669529663687f

// Static device scratch (allocation-free per harness rules), 16B-aligned for
// vector/cp.async access. All token-major [bh][token][d] half layouts.
__device__ __align__(16) __half g_Qh[(size_t)B_ * NH * N_ * D_];
__device__ __align__(16) __half g_Kh[(size_t)B_ * NH * S_TOT * D_];
__device__ __align__(16) __half g_Vh[(size_t)B_ * NH * S_TOT * D_];
__device__ __align__(16) __half g_Onh[(size_t)B_ * N_ * C_];  // [b][n][c]

// ---------------------------------------------------------------------------
// helpers
// ---------------------------------------------------------------------------
__device__ __forceinline__ uint32_t packh2(float lo, float hi) {
  uint32_t r;
  asm("{ .reg .f16 a,b; cvt.rn.f16.f32 a, %1; cvt.rn.f16.f32 b, %2; "
      "mov.b32 %0, {a,b}; }"
      : "=r"(r) : "f"(lo), "f"(hi));
  return r;
}

__device__ __forceinline__ void ldsm4(uint32_t r[4], const __half* p) {
  uint32_t a = (uint32_t)__cvta_generic_to_shared(p);
  asm volatile(
      "ldmatrix.sync.aligned.m8n8.x4.shared.b16 {%0,%1,%2,%3}, [%4];"
      : "=r"(r[0]), "=r"(r[1]), "=r"(r[2]), "=r"(r[3]) : "r"(a));
}

__device__ __forceinline__ void ldsm4t(uint32_t r[4], const __half* p) {
  uint32_t a = (uint32_t)__cvta_generic_to_shared(p);
  asm volatile(
      "ldmatrix.sync.aligned.m8n8.x4.trans.shared.b16 {%0,%1,%2,%3}, [%4];"
      : "=r"(r[0]), "=r"(r[1]), "=r"(r[2]), "=r"(r[3]) : "r"(a));
}

__device__ __forceinline__ void mma16816(float c[4], const uint32_t a[4],
                                         uint32_t b0, uint32_t b1) {
  asm volatile(
      "mma.sync.aligned.m16n8k16.row.col.f32.f16.f16.f32 "
      "{%0,%1,%2,%3},{%4,%5,%6,%7},{%8,%9},{%0,%1,%2,%3};"
      : "+f"(c[0]), "+f"(c[1]), "+f"(c[2]), "+f"(c[3])
      : "r"(a[0]), "r"(a[1]), "r"(a[2]), "r"(a[3]), "r"(b0), "r"(b1));
}

__device__ __forceinline__ void cp16(uint32_t dst, const void* src,
                                     int src_bytes) {
  asm volatile("cp.async.cg.shared.global [%0], [%1], 16, %2;" ::
                   "r"(dst), "l"(src), "r"(src_bytes));
}
__device__ __forceinline__ void cp_commit() {
  asm volatile("cp.async.commit_group;");
}

// ---------------------------------------------------------------------------
// QKV projection (fp16 mma): y[o][p] = sum_c w[o][c] x[c][p] + bias[o]
// CTA tile 64 o x 128 p, 8 warps (wm 0-3 x wn 0-1). Scatter half epilogue.
// ---------------------------------------------------------------------------
__global__ __launch_bounds__(256) void qkv_mma_kernel(
    const float* __restrict__ x, const float* __restrict__ w,
    const float* __restrict__ bias) {
  __shared__ __half Ws[64 * 40];    // [o][c-chunk32], pad 40
  __shared__ __half Xs[32 * 136];   // [c][p 128], pad 136
  int b = blockIdx.z;
  int ob = blockIdx.y * 64;
  int pb = blockIdx.x * 128;
  int tid = threadIdx.x, lane = tid & 31, wrp = tid >> 5;
  int wm = wrp & 3, wn = wrp >> 2;
  int g = lane >> 2, t4 = lane & 3;
  const float* xb = x + (size_t)b * C_ * N_;

  float acc[8][4];
#pragma unroll
  for (int i = 0; i < 8; i++)
#pragma unroll
    for (int j = 0; j < 4; j++) acc[i][j] = 0.f;

  for (int kk = 0; kk < C_; kk += 32) {
    // Ws: 64 rows x 32 c (fp32 -> fp16)
    {
      int o = tid >> 2, c0 = (tid & 3) * 8;
      const float* wp = w + (size_t)(ob + o) * C_ + kk + c0;
      float4 w0 = *(const float4*)wp;
      float4 w1 = *(const float4*)(wp + 4);
      uint4 hv;
      hv.x = packh2(w0.x, w0.y); hv.y = packh2(w0.z, w0.w);
      hv.z = packh2(w1.x, w1.y); hv.w = packh2(w1.z, w1.w);
      *(uint4*)&Ws[o * 40 + c0] = hv;
    }
    // Xs: 32 c x 128 p
#pragma unroll
    for (int q = 0; q < 4; q++) {
      int f = tid + q * 256;
      int c = f >> 5, p4 = (f & 31) * 4;
      float4 v = *(const float4*)(xb + (size_t)(kk + c) * N_ + pb + p4);
      uint2 hv;
      hv.x = packh2(v.x, v.y); hv.y = packh2(v.z, v.w);
      *(uint2*)&Xs[c * 136 + p4] = hv;
    }
    __syncthreads();
#pragma unroll
    for (int kt = 0; kt < 2; kt++) {
      uint32_t a[4];
      {
        int row = wm * 16 + (lane & 15);
        int col = kt * 16 + ((lane & 16) ? 8 : 0);
        ldsm4(a, &Ws[row * 40 + col]);
      }
#pragma unroll
      for (int pr = 0; pr < 4; pr++) {
        uint32_t r[4];
        int row = kt * 16 + (lane & 15);
        int colp = wn * 64 + pr * 16 + ((lane & 16) ? 8 : 0);
        ldsm4t(r, &Xs[row * 136 + colp]);
        mma16816(acc[2 * pr], a, r[0], r[1]);
        mma16816(acc[2 * pr + 1], a, r[2], r[3]);
      }
    }
    __syncthreads();
  }

  // Epilogue: bias, scale Q, scatter half into [bh][token][d]
  int o0 = ob + wm * 16 + g;
  float bv0 = bias[o0], bv1 = bias[o0 + 8];
#pragma unroll
  for (int rs = 0; rs < 2; rs++) {
    int o = rs ? (o0 + 8) : o0;
    float bv = rs ? bv1 : bv0;
    int region = o >> 8;
    int rem = o & 255;
    int hh = rem >> 5, dd = rem & 31;
    int bh = b * NH + hh;
    __half* base;
    size_t tokoff;
    float sc = 1.f;
    if (region == 0) {
      base = g_Qh; tokoff = (size_t)bh * N_; sc = SCALE_;
    } else if (region == 1) {
      base = g_Kh; tokoff = (size_t)bh * S_TOT + NM_;
    } else {
      base = g_Vh; tokoff = (size_t)bh * S_TOT + NM_;
    }
#pragma unroll
    for (int nt = 0; nt < 8; nt++) {
      int p = pb + wn * 64 + nt * 8 + 2 * t4;
      float v0 = (acc[nt][rs * 2 + 0] + bv) * sc;
      float v1 = (acc[nt][rs * 2 + 1] + bv) * sc;
      base[(tokoff + p) * D_ + dd] = __float2half_rn(v0);
      base[(tokoff + p + 1) * D_ + dd] = __float2half_rn(v1);
    }
  }
}

// ---------------------------------------------------------------------------
// Memory kv tokens -> s = 0..3 of g_Kh / g_Vh for every batch.
// ---------------------------------------------------------------------------
__global__ void memtok_kernel(const float* __restrict__ mem_kv) {
  int idx = blockIdx.x * blockDim.x + threadIdx.x;
  if (idx >= 2 * NH * NM_ * D_) return;
  int d = idx & 31, mm = (idx >> 5) & 3, hh = (idx >> 7) & 7, kv = idx >> 10;
  __half v = __float2half_rn(mem_kv[idx]);
#pragma unroll
  for (int b = 0; b < B_; b++) {
    int bh = b * NH + hh;
    if (kv == 0)
      g_Kh[((size_t)bh * S_TOT + mm) * D_ + d] = v;
    else
      g_Vh[((size_t)bh * S_TOT + mm) * D_ + d] = v;
  }
}

// ---------------------------------------------------------------------------
// Flash attention, fp16 m16n8k16 + ldmatrix + cp.async double buffer.
// CTA 256 thr (8 warps x 16 q rows = 128 q). K-tile 64 keys.
// ---------------------------------------------------------------------------
#define ATT_STRIDE 40  // halves per row (80 B): ldmatrix conflict-free

__global__ __launch_bounds__(256) void attn_mma_kernel() {
  __shared__ __half Qs[128 * ATT_STRIDE];
  __shared__ __half Ks[2][64 * ATT_STRIDE];
  __shared__ __half Vs[2][64 * ATT_STRIDE];

  int b = blockIdx.z, h = blockIdx.y;
  int bh = b * NH + h;
  int qbase = blockIdx.x * 128;
  int tid = threadIdx.x, lane = tid & 31, w = tid >> 5;
  int g = lane >> 2, t4 = lane & 3;

  const __half* Qg = g_Qh + (size_t)bh * N_ * D_;
  const __half* Kg = g_Kh + (size_t)bh * S_TOT * D_;
  const __half* Vg = g_Vh + (size_t)bh * S_TOT * D_;

  int row64 = tid >> 2, ch = tid & 3;

  // G0: Q tile (128 rows x 64 B)
#pragma unroll
  for (int q = 0; q < 2; q++) {
    int idx = tid + q * 256;
    int r = idx >> 2, c = idx & 3;
    uint32_t dst = (uint32_t)__cvta_generic_to_shared(
        &Qs[r * ATT_STRIDE + c * 8]);
    cp16(dst, Qg + ((size_t)qbase + r) * D_ + c * 8, 16);
  }
  cp_commit();

  // G1: KV tile 0
  {
    int j = row64;  // kbase 0
    uint32_t dk = (uint32_t)__cvta_generic_to_shared(
        &Ks[0][j * ATT_STRIDE + ch * 8]);
    uint32_t dv = (uint32_t)__cvta_generic_to_shared(
        &Vs[0][j * ATT_STRIDE + ch * 8]);
    cp16(dk, Kg + (size_t)j * D_ + ch * 8, 16);
    cp16(dv, Vg + (size_t)j * D_ + ch * 8, 16);
  }
  cp_commit();

  asm volatile("cp.async.wait_group 1;");  // Q done
  __syncthreads();

  // Q A-frags: qa[kt][4] (kt: d 0-15 / 16-31)
  uint32_t qa[2][4];
#pragma unroll
  for (int kt = 0; kt < 2; kt++) {
    int r = w * 16 + (lane & 15);
    int c = kt * 16 + ((lane & 16) ? 8 : 0);
    ldsm4(qa[kt], &Qs[r * ATT_STRIDE + c]);
  }

  float oc[4][4];
#pragma unroll
  for (int nt = 0; nt < 4; nt++)
#pragma unroll
    for (int e = 0; e < 4; e++) oc[nt][e] = 0.f;
  float m0 = -1e30f, m1 = -1e30f, l0 = 0.f, l1 = 0.f;

  const int NTILES = (S_TOT + 63) / 64;  // 65
#pragma unroll 1
  for (int t = 0; t < NTILES; t++) {
    int buf = t & 1;
    // prefetch t+1
    if (t + 1 < NTILES) {
      int nb = buf ^ 1;
      int j = (t + 1) * 64 + row64;
      int ok = (j < S_TOT) ? 16 : 0;
      int jc = (j < S_TOT) ? j : (S_TOT - 1);
      uint32_t dk = (uint32_t)__cvta_generic_to_shared(
          &Ks[nb][row64 * ATT_STRIDE + ch * 8]);
      uint32_t dv = (uint32_t)__cvta_generic_to_shared(
          &Vs[nb][row64 * ATT_STRIDE + ch * 8]);
      cp16(dk, Kg + (size_t)jc * D_ + ch * 8, ok);
      cp16(dv, Vg + (size_t)jc * D_ + ch * 8, ok);
      cp_commit();
      asm volatile("cp.async.wait_group 1;");
    } else {
      asm volatile("cp.async.wait_group 0;");
    }
    __syncthreads();

    const __half* Kb = &Ks[buf][0];
    const __half* Vb = &Vs[buf][0];

    // ---- S = Q K^T ----
    float sc[8][4];
#pragma unroll
    for (int nt = 0; nt < 8; nt++)
#pragma unroll
      for (int e = 0; e < 4; e++) sc[nt][e] = 0.f;
#pragma unroll
    for (int kt = 0; kt < 2; kt++) {
#pragma unroll
      for (int pr = 0; pr < 4; pr++) {
        uint32_t r[4];
        int jrow = pr * 16 + (lane & 7) + ((lane & 16) ? 8 : 0);
        int dcol = kt * 16 + ((lane & 8) ? 8 : 0);
        ldsm4(r, &Kb[jrow * ATT_STRIDE + dcol]);
        mma16816(sc[2 * pr], qa[kt], r[0], r[1]);
        mma16816(sc[2 * pr + 1], qa[kt], r[2], r[3]);
      }
    }

    // ---- mask (last tile only) ----
    int kbase = t * 64;
    if (kbase + 64 > S_TOT) {
#pragma unroll
      for (int nt = 0; nt < 8; nt++) {
        int col = kbase + 8 * nt + 2 * t4;
        if (col >= S_TOT) { sc[nt][0] = -1e30f; sc[nt][2] = -1e30f; }
        if (col + 1 >= S_TOT) { sc[nt][1] = -1e30f; sc[nt][3] = -1e30f; }
      }
    }

    // ---- online softmax (rows g and g+8) ----
    float mx0 = -1e30f, mx1 = -1e30f;
#pragma unroll
    for (int nt = 0; nt < 8; nt++) {
      mx0 = fmaxf(mx0, fmaxf(sc[nt][0], sc[nt][1]));
      mx1 = fmaxf(mx1, fmaxf(sc[nt][2], sc[nt][3]));
    }
    mx0 = fmaxf(mx0, __shfl_xor_sync(0xffffffffu, mx0, 1));
    mx0 = fmaxf(mx0, __shfl_xor_sync(0xffffffffu, mx0, 2));
    mx1 = fmaxf(mx1, __shfl_xor_sync(0xffffffffu, mx1, 1));
    mx1 = fmaxf(mx1, __shfl_xor_sync(0xffffffffu, mx1, 2));
    float mn0 = fmaxf(m0, mx0), mn1 = fmaxf(m1, mx1);
    float al0 = __expf(m0 - mn0), al1 = __expf(m1 - mn1);
    m0 = mn0; m1 = mn1;
    float rs0 = 0.f, rs1 = 0.f;
#pragma unroll
    for (int nt = 0; nt < 8; nt++) {
      sc[nt][0] = __expf(sc[nt][0] - mn0);
      sc[nt][1] = __expf(sc[nt][1] - mn0);
      sc[nt][2] = __expf(sc[nt][2] - mn1);
      sc[nt][3] = __expf(sc[nt][3] - mn1);
      rs0 += sc[nt][0] + sc[nt][1];
      rs1 += sc[nt][2] + sc[nt][3];
    }
    rs0 += __shfl_xor_sync(0xffffffffu, rs0, 1);
    rs0 += __shfl_xor_sync(0xffffffffu, rs0, 2);
    rs1 += __shfl_xor_sync(0xffffffffu, rs1, 1);
    rs1 += __shfl_xor_sync(0xffffffffu, rs1, 2);
    l0 = l0 * al0 + rs0;
    l1 = l1 * al1 + rs1;

#pragma unroll
    for (int nt = 0; nt < 4; nt++) {
      oc[nt][0] *= al0; oc[nt][1] *= al0;
      oc[nt][2] *= al1; oc[nt][3] *= al1;
    }

    // ---- PV: P C-frag == A-frag (no shuffles), V via ldmatrix.trans ----
#pragma unroll
    for (int k4 = 0; k4 < 4; k4++) {
      uint32_t pa[4];
      pa[0] = packh2(sc[2 * k4][0], sc[2 * k4][1]);
      pa[1] = packh2(sc[2 * k4][2], sc[2 * k4][3]);
      pa[2] = packh2(sc[2 * k4 + 1][0], sc[2 * k4 + 1][1]);
      pa[3] = packh2(sc[2 * k4 + 1][2], sc[2 * k4 + 1][3]);
#pragma unroll
      for (int dh = 0; dh < 2; dh++) {
        uint32_t r[4];
        int jrow = k4 * 16 + (lane & 15);
        int dcol = dh * 16 + ((lane & 16) ? 8 : 0);
        ldsm4t(r, &Vb[jrow * ATT_STRIDE + dcol]);
        mma16816(oc[2 * dh], pa, r[0], r[1]);
        mma16816(oc[2 * dh + 1], pa, r[2], r[3]);
      }
    }
    __syncthreads();  // done with buf before next prefetch overwrites
  }

  // ---- normalize, write half to g_Onh[b][n][h*32+dv] ----
  float inv0 = 1.0f / l0, inv1 = 1.0f / l1;
  int row0 = qbase + 16 * w + g;
  int row1 = row0 + 8;
#pragma unroll
  for (int nt = 0; nt < 4; nt++) {
    int dv = 8 * nt + 2 * t4;
    __half2 v0 = __floats2half2_rn(oc[nt][0] * inv0, oc[nt][1] * inv0);
    __half2 v1 = __floats2half2_rn(oc[nt][2] * inv1, oc[nt][3] * inv1);
    *(__half2*)(g_Onh + ((size_t)b * N_ + row0) * C_ + h * D_ + dv) = v0;
    *(__half2*)(g_Onh + ((size_t)b * N_ + row1) * C_ + h * D_ + dv) = v1;
  }
}

// ---------------------------------------------------------------------------
// Output projection (fp16 mma): out[o][p] = sum_c Onn[p][c] w_out[o][c] + b
// CTA tile 64 o x 128 p.
// ---------------------------------------------------------------------------
__global__ __launch_bounds__(256) void outproj_mma_kernel(
    const float* __restrict__ w, const float* __restrict__ bias,
    float* __restrict__ out) {
  __shared__ __half Ws[64 * 40];    // [o][c-chunk32]
  __shared__ __half Os[128 * 40];   // [p][c-chunk32]
  int b = blockIdx.z;
  int ob = blockIdx.y * 64;
  int pb = blockIdx.x * 128;
  int tid = threadIdx.x, lane = tid & 31, wrp = tid >> 5;
  int wm = wrp & 3, wn = wrp >> 2;
  int g = lane >> 2, t4 = lane & 3;

  float acc[8][4];
#pragma unroll
  for (int i = 0; i < 8; i++)
#pragma unroll
    for (int j = 0; j < 4; j++) acc[i][j] = 0.f;

  for (int kk = 0; kk < C_; kk += 32) {
    {
      int o = tid >> 2, c0 = (tid & 3) * 8;
      const float* wp = w + (size_t)(ob + o) * C_ + kk + c0;
      float4 w0 = *(const float4*)wp;
      float4 w1 = *(const float4*)(wp + 4);
      uint4 hv;
      hv.x = packh2(w0.x, w0.y); hv.y = packh2(w0.z, w0.w);
      hv.z = packh2(w1.x, w1.y); hv.w = packh2(w1.z, w1.w);
      *(uint4*)&Ws[o * 40 + c0] = hv;
    }
#pragma unroll
    for (int q = 0; q < 2; q++) {
      int idx = tid + q * 256;
      int r = idx >> 2, c = idx & 3;
      const __half* src =
          g_Onh + ((size_t)b * N_ + pb + r) * C_ + kk + c * 8;
      *(uint4*)&Os[r * 40 + c * 8] = *(const uint4*)src;
    }
    __syncthreads();
#pragma unroll
    for (int kt = 0; kt < 2; kt++) {
      uint32_t a[4];
      {
        int row = wm * 16 + (lane & 15);
        int col = kt * 16 + ((lane & 16) ? 8 : 0);
        ldsm4(a, &Ws[row * 40 + col]);
      }
#pragma unroll
      for (int pr = 0; pr < 4; pr++) {
        uint32_t r[4];
        int prow = wn * 64 + pr * 16 + (lane & 7) + ((lane & 16) ? 8 : 0);
        int ccol = kt * 16 + ((lane & 8) ? 8 : 0);
        ldsm4(r, &Os[prow * 40 + ccol]);
        mma16816(acc[2 * pr], a, r[0], r[1]);
        mma16816(acc[2 * pr + 1], a, r[2], r[3]);
      }
    }
    __syncthreads();
  }

  int o0 = ob + wm * 16 + g;
  float bv0 = bias[o0], bv1 = bias[o0 + 8];
#pragma unroll
  for (int nt = 0; nt < 8; nt++) {
    int p = pb + wn * 64 + nt * 8 + 2 * t4;
    float2 v0 = make_float2(acc[nt][0] + bv0, acc[nt][1] + bv0);
    float2 v1 = make_float2(acc[nt][2] + bv1, acc[nt][3] + bv1);
    *(float2*)(out + ((size_t)(b * C_ + o0)) * N_ + p) = v0;
    *(float2*)(out + ((size_t)(b * C_ + o0 + 8)) * N_ + p) = v1;
  }
}

// ---------------------------------------------------------------------------
extern "C" void kernel_launch(void* const* d_in, const int* in_sizes, int n_in,
                              void* d_out, int out_size) {
  const float* x = (const float*)d_in[0];
  const float* w_qkv = (const float*)d_in[1];
  const float* b_qkv = (const float*)d_in[2];
  const float* mem_kv = (const float*)d_in[3];
  const float* w_out = (const float*)d_in[4];
  const float* b_out = (const float*)d_in[5];
  float* out = (float*)d_out;

  dim3 g1(N_ / 128, O3_ / 64, B_);  // 32 x 12 x 4
  qkv_mma_kernel<<<g1, 256>>>(x, w_qkv, b_qkv);

  memtok_kernel<<<2, 1024>>>(mem_kv);

  dim3 g2(N_ / 128, NH, B_);  // 32 x 8 x 4
  attn_mma_kernel<<<g2, 256>>>();

  dim3 g3(N_ / 128, C_ / 64, B_);  // 32 x 4 x 4
  outproj_mma_kernel<<<g3, 256>>>(w_out, b_out, out);
}